// round 2
// baseline (speedup 1.0000x reference)
#include <cuda_runtime.h>
#include <math.h>

#define D     512
#define NE    8192
#define NMAX  32768
#define BM    64
#define BN    256
#define KT    64
#define EPAD  68        // stride % 32 == 4 -> conflict-free float4 phases
#define BETA  0.25f

typedef unsigned long long u64;

__device__ float g_inv[NE];
__device__ float g_counts[NE];
__device__ int   g_idx[NMAX];
__device__ float g_loss;

// packed f32x2 helpers
__device__ __forceinline__ u64 pk2(float x, float y) {
    return __double_as_longlong(__hiloint2double(__float_as_int(y), __float_as_int(x)));
}
__device__ __forceinline__ float unpk_lo(u64 v) {
    return __int_as_float(__double2loint(__longlong_as_double(v)));
}
__device__ __forceinline__ float unpk_hi(u64 v) {
    return __int_as_float(__double2hiint(__longlong_as_double(v)));
}
__device__ __forceinline__ void ffma2(u64& d, u64 a, u64 b) {
    asm("fma.rn.f32x2 %0, %1, %2, %0;" : "+l"(d) : "l"(a), "l"(b));
}

// ---------------- zero scratch ----------------
__global__ void zero_kernel() {
    int i = blockIdx.x * blockDim.x + threadIdx.x;
    if (i < NE) g_counts[i] = 0.0f;
    if (i == 0) g_loss = 0.0f;
}

// ---------------- emb inverse norms ----------------
__global__ void embnorm_kernel(const float* __restrict__ emb) {
    int e = blockIdx.x;
    const float4* row = (const float4*)(emb + (size_t)e * D);
    float ss = 0.0f;
    for (int i = threadIdx.x; i < D / 4; i += 128) {
        float4 v = row[i];
        ss += v.x * v.x + v.y * v.y + v.z * v.z + v.w * v.w;
    }
    for (int o = 16; o; o >>= 1) ss += __shfl_down_sync(0xffffffffu, ss, o);
    __shared__ float s[4];
    if ((threadIdx.x & 31) == 0) s[threadIdx.x >> 5] = ss;
    __syncthreads();
    if (threadIdx.x == 0) {
        ss = s[0] + s[1] + s[2] + s[3];
        g_inv[e] = 1.0f / fmaxf(sqrtf(ss), 1e-12f);
    }
}

// ---------------- fused GEMM + argmax (packed f32x2) ----------------
// CTA: 64 z rows (full K in smem), streams emb in 256-col tiles, KT=64 k-chunks.
// 256 threads, 8x8 micro-tile each; acc holds (even-k, odd-k) packed partials.
extern __shared__ float smem_dyn[];

__global__ void __launch_bounds__(256, 1)
argmax_kernel(const float* __restrict__ z, const float* __restrict__ emb) {
    float* z_s = smem_dyn;                 // [BM][D]        = 128 KB
    float* e_s = smem_dyn + BM * D;        // [BN][EPAD]     ~ 68 KB

    const int tid  = threadIdx.x;
    const int ty   = tid >> 5;             // 0..7  (row group; rows ty*8..ty*8+7)
    const int tx   = tid & 31;             // 0..31 (col lane; cols tx + 32*c)
    const int row0 = blockIdx.x * BM;

    // load the z slab (coalesced float4)
    {
        const float4* zg  = (const float4*)(z + (size_t)row0 * D);
        float4*       zs4 = (float4*)z_s;
        for (int i = tid; i < BM * D / 4; i += 256) zs4[i] = zg[i];
    }
    __syncthreads();

    float bestv[8];
    int   besti[8];
#pragma unroll
    for (int r = 0; r < 8; r++) { bestv[r] = -INFINITY; besti[r] = 0; }

    for (int e0 = 0; e0 < NE; e0 += BN) {
        u64 acc[8][8];
#pragma unroll
        for (int r = 0; r < 8; r++)
#pragma unroll
            for (int c = 0; c < 8; c++) acc[r][c] = 0ULL;

        for (int kt = 0; kt < D; kt += KT) {
            // stage e tile: [BN][KT] -> e_s[c][EPAD]
            for (int i = tid; i < BN * KT / 4; i += 256) {
                int c = i / (KT / 4);
                int q = i % (KT / 4);
                float4 v = *(const float4*)(emb + (size_t)(e0 + c) * D + kt + q * 4);
                *(float4*)(e_s + c * EPAD + q * 4) = v;
            }
            __syncthreads();

#pragma unroll 4
            for (int kk = 0; kk < KT; kk += 4) {
                u64 za[8], zb[8], ea[8], eb[8];
#pragma unroll
                for (int r = 0; r < 8; r++) {
                    float4 v = *(const float4*)(z_s + (ty * 8 + r) * D + kt + kk);
                    za[r] = pk2(v.x, v.y);
                    zb[r] = pk2(v.z, v.w);
                }
#pragma unroll
                for (int c = 0; c < 8; c++) {
                    float4 v = *(const float4*)(e_s + (tx + 32 * c) * EPAD + kk);
                    ea[c] = pk2(v.x, v.y);
                    eb[c] = pk2(v.z, v.w);
                }
#pragma unroll
                for (int r = 0; r < 8; r++)
#pragma unroll
                    for (int c = 0; c < 8; c++) {
                        ffma2(acc[r][c], za[r], ea[c]);
                        ffma2(acc[r][c], zb[r], eb[c]);
                    }
            }
            __syncthreads();
        }

        // scale by 1/||emb|| and update running argmax
#pragma unroll
        for (int c = 0; c < 8; c++) {
            int   col = e0 + tx + 32 * c;
            float inv = __ldg(&g_inv[col]);
#pragma unroll
            for (int r = 0; r < 8; r++) {
                float s = (unpk_lo(acc[r][c]) + unpk_hi(acc[r][c])) * inv;
                if (s > bestv[r] || (s == bestv[r] && col < besti[r])) {
                    bestv[r] = s;
                    besti[r] = col;
                }
            }
        }
    }

    // cross-thread (tx) reduction per row — reuse e_s region
    float* sv = e_s;                        // [BM][32]
    int*   si = (int*)(e_s + BM * 32);      // [BM][32]
    __syncthreads();
#pragma unroll
    for (int r = 0; r < 8; r++) {
        sv[(ty * 8 + r) * 32 + tx] = bestv[r];
        si[(ty * 8 + r) * 32 + tx] = besti[r];
    }
    __syncthreads();
    if (tid < BM) {
        float bv = -INFINITY;
        int   bi = 0x7fffffff;
        for (int j = 0; j < 32; j++) {
            float v = sv[tid * 32 + j];
            int   ii = si[tid * 32 + j];
            if (v > bv || (v == bv && ii < bi)) { bv = v; bi = ii; }
        }
        g_idx[row0 + tid] = bi;
    }
}

// ---------------- gather + z_q_st + loss + counts + idx out ----------------
__global__ void gather_kernel(const float* __restrict__ z,
                              const float* __restrict__ emb,
                              float* __restrict__ out_zq,   // (may be unaligned base)
                              float* __restrict__ out_idx) {
    __shared__ float sred[4];
    __shared__ float sbc;
    int n = blockIdx.x;
    int t = threadIdx.x;   // 128 threads, 4 floats each
    int e = g_idx[n];
    float inv_e = g_inv[e];

    float4 zv = ((const float4*)(z + (size_t)n * D))[t];
    float ss = zv.x * zv.x + zv.y * zv.y + zv.z * zv.z + zv.w * zv.w;
    for (int o = 16; o; o >>= 1) ss += __shfl_down_sync(0xffffffffu, ss, o);
    if ((t & 31) == 0) sred[t >> 5] = ss;
    __syncthreads();
    if (t == 0) sbc = sred[0] + sred[1] + sred[2] + sred[3];
    __syncthreads();
    float zinv = 1.0f / fmaxf(sqrtf(sbc), 1e-12f);

    float4 q = ((const float4*)(emb + (size_t)e * D))[t];
    q.x *= inv_e; q.y *= inv_e; q.z *= inv_e; q.w *= inv_e;

    // scalar stores: out_zq base = d_out+1 is only 4B aligned
    float* o = out_zq + (size_t)n * D + t * 4;
    o[0] = q.x; o[1] = q.y; o[2] = q.z; o[3] = q.w;

    float dx = q.x - zv.x * zinv;
    float dy = q.y - zv.y * zinv;
    float dz = q.z - zv.z * zinv;
    float dw = q.w - zv.w * zinv;
    float ls = dx * dx + dy * dy + dz * dz + dw * dw;
    for (int o2 = 16; o2; o2 >>= 1) ls += __shfl_down_sync(0xffffffffu, ls, o2);
    if ((t & 31) == 0) sred[t >> 5] = ls;
    __syncthreads();
    if (t == 0) {
        atomicAdd(&g_loss, sred[0] + sred[1] + sred[2] + sred[3]);
        atomicAdd(&g_counts[e], 1.0f);
        out_idx[n] = (float)e;
    }
}

// ---------------- loss / perplexity finalize ----------------
__global__ void finalize_kernel(float* __restrict__ out, int N) {
    __shared__ float sh[256];
    float h = 0.0f;
    float invN = 1.0f / (float)N;
    for (int i = threadIdx.x; i < NE; i += 256) {
        float p = g_counts[i] * invN;
        h -= p * logf(p + 1e-10f);
    }
    sh[threadIdx.x] = h;
    __syncthreads();
    for (int s = 128; s; s >>= 1) {
        if (threadIdx.x < s) sh[threadIdx.x] += sh[threadIdx.x + s];
        __syncthreads();
    }
    if (threadIdx.x == 0) {
        out[0] = g_loss * (1.0f + BETA) / ((float)N * (float)D);
        out[1 + (size_t)N * D + (size_t)N] = expf(sh[0]);
    }
}

// ---------------- launch ----------------
extern "C" void kernel_launch(void* const* d_in, const int* in_sizes, int n_in,
                              void* d_out, int out_size) {
    const float* z   = (const float*)d_in[0];
    const float* emb = (const float*)d_in[1];
    float* out = (float*)d_out;

    int ND = in_sizes[0];
    int N  = ND / D;            // 32768

    size_t smem = (size_t)(BM * D + BN * EPAD) * sizeof(float);
    cudaFuncSetAttribute(argmax_kernel,
                         cudaFuncAttributeMaxDynamicSharedMemorySize, (int)smem);

    zero_kernel<<<(NE + 255) / 256, 256>>>();
    embnorm_kernel<<<NE, 128>>>(emb);
    argmax_kernel<<<N / BM, 256, smem>>>(z, emb);
    // output layout (tuple order, all as float32):
    // [0] loss | [1 .. 1+N*D) z_q_st | [1+N*D .. 1+N*D+N) idx | [last] perplexity
    gather_kernel<<<N, 128>>>(z, emb, out + 1, out + 1 + (size_t)ND);
    finalize_kernel<<<1, 256>>>(out, N);
}

// round 4
// speedup vs baseline: 2.6776x; 2.6776x over previous
#include <cuda_runtime.h>
#include <cuda_bf16.h>
#include <cstdint>
#include <math.h>

#define D     512
#define NE    8192
#define NMAX  32768
#define BETA  0.25f

#define BM      256
#define BN      128
#define BK      64
#define NTILES  (NE / BN)          // 64
#define CHUNKS  24                 // per tile: 3 segments x 8 chunks of 64
#define TOTALG  (NTILES * CHUNKS)  // 1536

// ---------------- device scratch ----------------
__device__ __nv_bfloat16 g_z1[(size_t)NMAX * D];
__device__ __nv_bfloat16 g_z2[(size_t)NMAX * D];
__device__ __nv_bfloat16 g_e1[(size_t)NE * D];
__device__ __nv_bfloat16 g_e2[(size_t)NE * D];
__device__ float g_inv[NE];
__device__ float g_counts[NE];
__device__ int   g_idx[NMAX];
__device__ int   g_i1[NMAX];
__device__ int   g_i2[NMAX];
__device__ float g_loss;

// ---------------- PTX helpers ----------------
__device__ __forceinline__ uint32_t smem_u32(const void* p) {
    uint32_t a;
    asm("{ .reg .u64 t; cvta.to.shared.u64 t, %1; cvt.u32.u64 %0, t; }" : "=r"(a) : "l"(p));
    return a;
}
#define CP16(dst, src) \
    asm volatile("cp.async.cg.shared.global [%0], [%1], 16;" :: "r"(dst), "l"(src) : "memory")
#define CP_COMMIT() asm volatile("cp.async.commit_group;" ::: "memory")
#define CP_WAIT(n)  asm volatile("cp.async.wait_group %0;" :: "n"(n) : "memory")

__device__ __forceinline__ void ldsm_x4(uint32_t& r0, uint32_t& r1, uint32_t& r2, uint32_t& r3,
                                        uint32_t addr) {
    asm volatile("ldmatrix.sync.aligned.m8n8.x4.shared.b16 {%0,%1,%2,%3}, [%4];"
                 : "=r"(r0), "=r"(r1), "=r"(r2), "=r"(r3) : "r"(addr));
}
__device__ __forceinline__ void mma_bf16(float* d, uint32_t a0, uint32_t a1, uint32_t a2,
                                         uint32_t a3, uint32_t b0, uint32_t b1) {
    asm volatile("mma.sync.aligned.m16n8k16.row.col.f32.bf16.bf16.f32 "
                 "{%0,%1,%2,%3}, {%4,%5,%6,%7}, {%8,%9}, {%0,%1,%2,%3};"
                 : "+f"(d[0]), "+f"(d[1]), "+f"(d[2]), "+f"(d[3])
                 : "r"(a0), "r"(a1), "r"(a2), "r"(a3), "r"(b0), "r"(b1));
}

// ---------------- small kernels ----------------
__global__ void zero_kernel() {
    int i = blockIdx.x * blockDim.x + threadIdx.x;
    if (i < NE) g_counts[i] = 0.0f;
    if (i == 0) g_loss = 0.0f;
}

__global__ void embnorm_kernel(const float* __restrict__ emb) {
    int e = blockIdx.x;
    const float4* row = (const float4*)(emb + (size_t)e * D);
    float ss = 0.0f;
    for (int i = threadIdx.x; i < D / 4; i += 128) {
        float4 v = row[i];
        ss += v.x * v.x + v.y * v.y + v.z * v.z + v.w * v.w;
    }
    for (int o = 16; o; o >>= 1) ss += __shfl_down_sync(0xffffffffu, ss, o);
    __shared__ float s[4];
    if ((threadIdx.x & 31) == 0) s[threadIdx.x >> 5] = ss;
    __syncthreads();
    if (threadIdx.x == 0) {
        ss = s[0] + s[1] + s[2] + s[3];
        g_inv[e] = 1.0f / fmaxf(sqrtf(ss), 1e-12f);
    }
}

__device__ __forceinline__ void split4(float4 v, __nv_bfloat162* H, __nv_bfloat162* L, size_t i2) {
    __nv_bfloat16 h0 = __float2bfloat16_rn(v.x), h1 = __float2bfloat16_rn(v.y);
    __nv_bfloat16 h2 = __float2bfloat16_rn(v.z), h3 = __float2bfloat16_rn(v.w);
    __nv_bfloat16 l0 = __float2bfloat16_rn(v.x - __bfloat162float(h0));
    __nv_bfloat16 l1 = __float2bfloat16_rn(v.y - __bfloat162float(h1));
    __nv_bfloat16 l2 = __float2bfloat16_rn(v.z - __bfloat162float(h2));
    __nv_bfloat16 l3 = __float2bfloat16_rn(v.w - __bfloat162float(h3));
    H[i2]     = __nv_bfloat162(h0, h1);
    H[i2 + 1] = __nv_bfloat162(h2, h3);
    L[i2]     = __nv_bfloat162(l0, l1);
    L[i2 + 1] = __nv_bfloat162(l2, l3);
}

__global__ void split_z_kernel(const float* __restrict__ z) {
    size_t i = (size_t)blockIdx.x * blockDim.x + threadIdx.x;
    float4 v = ((const float4*)z)[i];
    split4(v, (__nv_bfloat162*)g_z1, (__nv_bfloat162*)g_z2, i * 2);
}
__global__ void split_e_kernel(const float* __restrict__ emb) {
    size_t i = (size_t)blockIdx.x * blockDim.x + threadIdx.x;
    float4 v = ((const float4*)emb)[i];
    split4(v, (__nv_bfloat162*)g_e1, (__nv_bfloat162*)g_e2, i * 2);
}

// ---------------- HMMA GEMM + fused top-2 argmax ----------------
// 128 persistent CTAs x 512 threads. CTA = 256-row strip, loops 64 N-tiles.
// Warp w: rows w*16..w*16+15 x all 128 tile cols. K = 1536 bf16 (split-concat).
// SMEM: double-buffered A(256x64) + B(128x64), XOR-swizzled for ldmatrix.
#define ABYTES  (BM * BK * 2)      // 32768
#define BBYTES  (BN * BK * 2)      // 16384
#define STAGE   (ABYTES + BBYTES)  // 49152
#define SMEM_SZ (2 * STAGE)        // 98304

extern __shared__ char smem_raw[];

struct Top2 { float v1, v2; int i1, i2; };

__device__ __forceinline__ void t2_update(Top2& t, float s, int col) {
    if (s > t.v1) { t.v2 = t.v1; t.i2 = t.i1; t.v1 = s; t.i1 = col; }
    else if (s > t.v2) { t.v2 = s; t.i2 = col; }
}
__device__ __forceinline__ void t2_merge(Top2& t, float w1, int j1, float w2, int j2) {
    if (w1 > t.v1) {
        float ov1 = t.v1; int oi1 = t.i1;
        t.v1 = w1; t.i1 = j1;
        if (ov1 > w2) { t.v2 = ov1; t.i2 = oi1; }
        else          { t.v2 = w2;  t.i2 = j2;  }
    } else if (w1 > t.v2) { t.v2 = w1; t.i2 = j1; }
    if (w2 > t.v2 && w2 <= t.v1 && j2 != t.i1) { /* covered above in else-branch; keep simple */ }
}

__device__ __forceinline__ void load_chunk(uint32_t sb, int g, int row0, int tid) {
    const int t   = g / CHUNKS;
    const int c   = g % CHUNKS;
    const int seg = c >> 3;
    const int kl  = (c & 7) * BK;
    const int e0  = t * BN;
    const int buf = g & 1;
    const __nv_bfloat16* za = (seg < 2)  ? g_z1 : g_z2;
    const __nv_bfloat16* eb = (seg == 1) ? g_e2 : g_e1;
    const uint32_t ab = sb + buf * STAGE;
    const uint32_t bb = ab + ABYTES;
#pragma unroll
    for (int it = 0; it < 4; it++) {           // A: 2048 x 16B
        int u = tid + it * 512;
        int m = u >> 3, q = u & 7;
        uint32_t dst = ab + m * 128 + ((q ^ (m & 7)) << 4);
        CP16(dst, za + (size_t)(row0 + m) * D + kl + q * 8);
    }
#pragma unroll
    for (int it = 0; it < 2; it++) {           // B: 1024 x 16B
        int u = tid + it * 512;
        int n = u >> 3, q = u & 7;
        uint32_t dst = bb + n * 128 + ((q ^ (n & 7)) << 4);
        CP16(dst, eb + (size_t)(e0 + n) * D + kl + q * 8);
    }
    CP_COMMIT();
}

__global__ void __launch_bounds__(512, 1) mma_argmax_kernel() {
    const uint32_t sb = smem_u32(smem_raw);
    const int tid  = threadIdx.x;
    const int wid  = tid >> 5;
    const int lane = tid & 31;
    const int row0 = blockIdx.x * BM;
    const int wrow = wid * 16;                 // warp's first row within strip

    // ldmatrix lane addressing (precomputed pieces)
    const int a_row = wrow + (lane & 15);
    const int a_kx  = (lane >> 4);             // 0/1 -> +8 in k
    const int b_row_base = ((lane >> 4) << 3) + (lane & 7);
    const int b_kx  = (lane >> 3) & 1;

    float acc[16][4];
#pragma unroll
    for (int f = 0; f < 16; f++)
#pragma unroll
        for (int j = 0; j < 4; j++) acc[f][j] = 0.0f;

    Top2 tA = {-INFINITY, -INFINITY, 0, 0};
    Top2 tB = {-INFINITY, -INFINITY, 0, 0};

    load_chunk(sb, 0, row0, tid);

    for (int g = 0; g < TOTALG; g++) {
        if (g + 1 < TOTALG) {
            load_chunk(sb, g + 1, row0, tid);
            CP_WAIT(1);
        } else {
            CP_WAIT(0);
        }
        __syncthreads();

        const uint32_t ab = sb + (g & 1) * STAGE;
        const uint32_t bb = ab + ABYTES;
#pragma unroll
        for (int s = 0; s < 4; s++) {
            uint32_t a0, a1, a2, a3;
            {
                int ku = s * 2 + a_kx;
                uint32_t addr = ab + a_row * 128 + ((ku ^ (a_row & 7)) << 4);
                ldsm_x4(a0, a1, a2, a3, addr);
            }
#pragma unroll
            for (int gn = 0; gn < 8; gn++) {
                uint32_t b0, b1, b2, b3;
                int n  = gn * 16 + b_row_base;
                int ku = s * 2 + b_kx;
                uint32_t addr = bb + n * 128 + ((ku ^ (n & 7)) << 4);
                ldsm_x4(b0, b1, b2, b3, addr);
                mma_bf16(acc[gn * 2],     a0, a1, a2, a3, b0, b1);
                mma_bf16(acc[gn * 2 + 1], a0, a1, a2, a3, b2, b3);
            }
        }

        if ((g % CHUNKS) == CHUNKS - 1) {
            // tile epilogue: scale by 1/||emb||, update top-2, reset acc
            const int e0 = (g / CHUNKS) * BN;
            const int c2 = (lane & 3) * 2;
#pragma unroll
            for (int f = 0; f < 16; f++) {
                int col0 = e0 + f * 8 + c2;
                float i0 = __ldg(&g_inv[col0]);
                float i1v = __ldg(&g_inv[col0 + 1]);
                t2_update(tA, acc[f][0] * i0,  col0);
                t2_update(tA, acc[f][1] * i1v, col0 + 1);
                t2_update(tB, acc[f][2] * i0,  col0);
                t2_update(tB, acc[f][3] * i1v, col0 + 1);
#pragma unroll
                for (int j = 0; j < 4; j++) acc[f][j] = 0.0f;
            }
        }
        __syncthreads();
    }

    // reduce top-2 across the 4 lanes sharing each row (lane%4 = 0..3)
#pragma unroll
    for (int o = 1; o < 4; o <<= 1) {
        float w1 = __shfl_xor_sync(0xffffffffu, tA.v1, o);
        int   j1 = __shfl_xor_sync(0xffffffffu, tA.i1, o);
        float w2 = __shfl_xor_sync(0xffffffffu, tA.v2, o);
        int   j2 = __shfl_xor_sync(0xffffffffu, tA.i2, o);
        t2_merge(tA, w1, j1, w2, j2);
        w1 = __shfl_xor_sync(0xffffffffu, tB.v1, o);
        j1 = __shfl_xor_sync(0xffffffffu, tB.i1, o);
        w2 = __shfl_xor_sync(0xffffffffu, tB.v2, o);
        j2 = __shfl_xor_sync(0xffffffffu, tB.i2, o);
        t2_merge(tB, w1, j1, w2, j2);
    }
    if ((lane & 3) == 0) {
        int rA = row0 + wrow + (lane >> 2);
        g_i1[rA] = tA.i1; g_i2[rA] = tA.i2;
        g_i1[rA + 8] = tB.i1; g_i2[rA + 8] = tB.i2;
    }
}

// ---------------- exact fp32 re-score of top-2 candidates ----------------
__global__ void fixup_kernel(const float* __restrict__ z, const float* __restrict__ emb) {
    int w    = (blockIdx.x * blockDim.x + threadIdx.x) >> 5;
    int lane = threadIdx.x & 31;
    int iA = g_i1[w], iB = g_i2[w];
    const float4* zr = (const float4*)(z + (size_t)w * D);
    const float4* ea = (const float4*)(emb + (size_t)iA * D);
    const float4* eb = (const float4*)(emb + (size_t)iB * D);
    float dA = 0.0f, dB = 0.0f;
    for (int k = lane; k < D / 4; k += 32) {
        float4 zv = zr[k], a = ea[k], b = eb[k];
        dA += zv.x * a.x + zv.y * a.y + zv.z * a.z + zv.w * a.w;
        dB += zv.x * b.x + zv.y * b.y + zv.z * b.z + zv.w * b.w;
    }
    for (int o = 16; o; o >>= 1) {
        dA += __shfl_down_sync(0xffffffffu, dA, o);
        dB += __shfl_down_sync(0xffffffffu, dB, o);
    }
    if (lane == 0) {
        float sA = dA * g_inv[iA];
        float sB = dB * g_inv[iB];
        int win = (sB > sA || (sB == sA && iB < iA)) ? iB : iA;
        g_idx[w] = win;
    }
}

// ---------------- gather + z_q_st + loss + counts + idx out ----------------
__global__ void gather_kernel(const float* __restrict__ z,
                              const float* __restrict__ emb,
                              float* __restrict__ out_zq,
                              float* __restrict__ out_idx) {
    __shared__ float sred[4];
    __shared__ float sbc;
    int n = blockIdx.x;
    int t = threadIdx.x;
    int e = g_idx[n];
    float inv_e = g_inv[e];

    float4 zv = ((const float4*)(z + (size_t)n * D))[t];
    float ss = zv.x * zv.x + zv.y * zv.y + zv.z * zv.z + zv.w * zv.w;
    for (int o = 16; o; o >>= 1) ss += __shfl_down_sync(0xffffffffu, ss, o);
    if ((t & 31) == 0) sred[t >> 5] = ss;
    __syncthreads();
    if (t == 0) sbc = sred[0] + sred[1] + sred[2] + sred[3];
    __syncthreads();
    float zinv = 1.0f / fmaxf(sqrtf(sbc), 1e-12f);

    float4 q = ((const float4*)(emb + (size_t)e * D))[t];
    q.x *= inv_e; q.y *= inv_e; q.z *= inv_e; q.w *= inv_e;

    float* o = out_zq + (size_t)n * D + t * 4;
    o[0] = q.x; o[1] = q.y; o[2] = q.z; o[3] = q.w;

    float dx = q.x - zv.x * zinv;
    float dy = q.y - zv.y * zinv;
    float dz = q.z - zv.z * zinv;
    float dw = q.w - zv.w * zinv;
    float ls = dx * dx + dy * dy + dz * dz + dw * dw;
    for (int o2 = 16; o2; o2 >>= 1) ls += __shfl_down_sync(0xffffffffu, ls, o2);
    if ((t & 31) == 0) sred[t >> 5] = ls;
    __syncthreads();
    if (t == 0) {
        atomicAdd(&g_loss, sred[0] + sred[1] + sred[2] + sred[3]);
        atomicAdd(&g_counts[e], 1.0f);
        out_idx[n] = (float)e;
    }
}

__global__ void finalize_kernel(float* __restrict__ out, int N) {
    __shared__ float sh[256];
    float h = 0.0f;
    float invN = 1.0f / (float)N;
    for (int i = threadIdx.x; i < NE; i += 256) {
        float p = g_counts[i] * invN;
        h -= p * logf(p + 1e-10f);
    }
    sh[threadIdx.x] = h;
    __syncthreads();
    for (int s = 128; s; s >>= 1) {
        if (threadIdx.x < s) sh[threadIdx.x] += sh[threadIdx.x + s];
        __syncthreads();
    }
    if (threadIdx.x == 0) {
        out[0] = g_loss * (1.0f + BETA) / ((float)N * (float)D);
        out[1 + (size_t)N * D + (size_t)N] = expf(sh[0]);
    }
}

// ---------------- launch ----------------
extern "C" void kernel_launch(void* const* d_in, const int* in_sizes, int n_in,
                              void* d_out, int out_size) {
    const float* z   = (const float*)d_in[0];
    const float* emb = (const float*)d_in[1];
    float* out = (float*)d_out;

    int ND = in_sizes[0];
    int N  = ND / D;            // 32768

    cudaFuncSetAttribute(mma_argmax_kernel,
                         cudaFuncAttributeMaxDynamicSharedMemorySize, SMEM_SZ);

    zero_kernel<<<(NE + 255) / 256, 256>>>();
    embnorm_kernel<<<NE, 128>>>(emb);
    split_z_kernel<<<(N * D / 4 + 255) / 256, 256>>>(z);
    split_e_kernel<<<(NE * D / 4 + 255) / 256, 256>>>(emb);
    mma_argmax_kernel<<<N / BM, 512, SMEM_SZ>>>();
    fixup_kernel<<<N / 8, 256>>>(z, emb);
    // output layout (tuple order, all as float32):
    // [0] loss | [1 .. 1+N*D) z_q_st | [1+N*D .. 1+N*D+N) idx | [last] perplexity
    gather_kernel<<<N, 128>>>(z, emb, out + 1, out + 1 + (size_t)ND);
    finalize_kernel<<<1, 256>>>(out, N);
}

// round 6
// speedup vs baseline: 2.7817x; 1.0389x over previous
#include <cuda_runtime.h>
#include <cuda_bf16.h>
#include <cstdint>
#include <math.h>

#define D     512
#define NE    8192
#define NMAX  32768
#define BETA  0.25f

#define BM      256
#define BN      128
#define BK      64
#define NTILES  (NE / BN)          // 64
#define CHUNKS  24                 // per tile: 3 segments x 8 chunks of 64
#define TOTALG  (NTILES * CHUNKS)  // 1536

// ---------------- device scratch ----------------
__device__ __nv_bfloat16 g_z1[(size_t)NMAX * D];
__device__ __nv_bfloat16 g_z2[(size_t)NMAX * D];
__device__ __nv_bfloat16 g_e1[(size_t)NE * D];
__device__ __nv_bfloat16 g_e2[(size_t)NE * D];
__device__ float g_inv[NE];
__device__ float g_counts[NE];
__device__ int   g_idx[NMAX];
__device__ int   g_i1[NMAX];
__device__ int   g_i2[NMAX];
__device__ float g_loss;

// ---------------- PTX helpers ----------------
__device__ __forceinline__ uint32_t smem_u32(const void* p) {
    uint32_t a;
    asm("{ .reg .u64 t; cvta.to.shared.u64 t, %1; cvt.u32.u64 %0, t; }" : "=r"(a) : "l"(p));
    return a;
}
#define CP16(dst, src) \
    asm volatile("cp.async.cg.shared.global [%0], [%1], 16;" :: "r"(dst), "l"(src) : "memory")
#define CP_COMMIT() asm volatile("cp.async.commit_group;" ::: "memory")
#define CP_WAIT(n)  asm volatile("cp.async.wait_group %0;" :: "n"(n) : "memory")

__device__ __forceinline__ void ldsm_x4(uint32_t& r0, uint32_t& r1, uint32_t& r2, uint32_t& r3,
                                        uint32_t addr) {
    asm volatile("ldmatrix.sync.aligned.m8n8.x4.shared.b16 {%0,%1,%2,%3}, [%4];"
                 : "=r"(r0), "=r"(r1), "=r"(r2), "=r"(r3) : "r"(addr));
}
__device__ __forceinline__ void mma_bf16(float* d, uint32_t a0, uint32_t a1, uint32_t a2,
                                         uint32_t a3, uint32_t b0, uint32_t b1) {
    asm volatile("mma.sync.aligned.m16n8k16.row.col.f32.bf16.bf16.f32 "
                 "{%0,%1,%2,%3}, {%4,%5,%6,%7}, {%8,%9}, {%0,%1,%2,%3};"
                 : "+f"(d[0]), "+f"(d[1]), "+f"(d[2]), "+f"(d[3])
                 : "r"(a0), "r"(a1), "r"(a2), "r"(a3), "r"(b0), "r"(b1));
}

// ---------------- small kernels ----------------
__global__ void zero_kernel() {
    int i = blockIdx.x * blockDim.x + threadIdx.x;
    if (i < NE) g_counts[i] = 0.0f;
    if (i == 0) g_loss = 0.0f;
}

__global__ void embnorm_kernel(const float* __restrict__ emb) {
    int e = blockIdx.x;
    const float4* row = (const float4*)(emb + (size_t)e * D);
    float ss = 0.0f;
    for (int i = threadIdx.x; i < D / 4; i += 128) {
        float4 v = row[i];
        ss += v.x * v.x + v.y * v.y + v.z * v.z + v.w * v.w;
    }
    for (int o = 16; o; o >>= 1) ss += __shfl_down_sync(0xffffffffu, ss, o);
    __shared__ float s[4];
    if ((threadIdx.x & 31) == 0) s[threadIdx.x >> 5] = ss;
    __syncthreads();
    if (threadIdx.x == 0) {
        ss = s[0] + s[1] + s[2] + s[3];
        g_inv[e] = 1.0f / fmaxf(sqrtf(ss), 1e-12f);
    }
}

__device__ __forceinline__ void split4(float4 v, __nv_bfloat162* H, __nv_bfloat162* L, size_t i2) {
    __nv_bfloat16 h0 = __float2bfloat16_rn(v.x), h1 = __float2bfloat16_rn(v.y);
    __nv_bfloat16 h2 = __float2bfloat16_rn(v.z), h3 = __float2bfloat16_rn(v.w);
    __nv_bfloat16 l0 = __float2bfloat16_rn(v.x - __bfloat162float(h0));
    __nv_bfloat16 l1 = __float2bfloat16_rn(v.y - __bfloat162float(h1));
    __nv_bfloat16 l2 = __float2bfloat16_rn(v.z - __bfloat162float(h2));
    __nv_bfloat16 l3 = __float2bfloat16_rn(v.w - __bfloat162float(h3));
    H[i2]     = __nv_bfloat162(h0, h1);
    H[i2 + 1] = __nv_bfloat162(h2, h3);
    L[i2]     = __nv_bfloat162(l0, l1);
    L[i2 + 1] = __nv_bfloat162(l2, l3);
}

__global__ void split_z_kernel(const float* __restrict__ z) {
    size_t i = (size_t)blockIdx.x * blockDim.x + threadIdx.x;
    float4 v = ((const float4*)z)[i];
    split4(v, (__nv_bfloat162*)g_z1, (__nv_bfloat162*)g_z2, i * 2);
}
__global__ void split_e_kernel(const float* __restrict__ emb) {
    size_t i = (size_t)blockIdx.x * blockDim.x + threadIdx.x;
    float4 v = ((const float4*)emb)[i];
    split4(v, (__nv_bfloat162*)g_e1, (__nv_bfloat162*)g_e2, i * 2);
}

// ---------------- HMMA GEMM + fused top-2 argmax ----------------
// 128 CTAs x 256 threads (8 warps). CTA = 256-row strip, loops 64 N-tiles.
// Warp w: rows w*32..w*32+31 (two 16-row A fragments) x all 128 tile cols.
// K = 1536 bf16 (split-concat: z1*e1 | z1*e2 | z2*e1).
// SMEM: double-buffered A(256x64) + B(128x64), XOR-swizzled for ldmatrix.
#define ABYTES  (BM * BK * 2)      // 32768
#define BBYTES  (BN * BK * 2)      // 16384
#define STAGE   (ABYTES + BBYTES)  // 49152
#define SMEM_SZ (2 * STAGE)        // 98304

extern __shared__ char smem_raw[];

struct Top2 { float v1, v2; int i1, i2; };

__device__ __forceinline__ void t2_update(Top2& t, float s, int col) {
    if (s > t.v1) { t.v2 = t.v1; t.i2 = t.i1; t.v1 = s; t.i1 = col; }
    else if (s > t.v2) { t.v2 = s; t.i2 = col; }
}
__device__ __forceinline__ void t2_merge(Top2& t, float w1, int j1, float w2, int j2) {
    if (w1 > t.v1) {
        float ov1 = t.v1; int oi1 = t.i1;
        t.v1 = w1; t.i1 = j1;
        if (ov1 > w2) { t.v2 = ov1; t.i2 = oi1; }
        else          { t.v2 = w2;  t.i2 = j2;  }
    } else if (w1 > t.v2) { t.v2 = w1; t.i2 = j1; }
}

__device__ __forceinline__ void load_chunk(uint32_t sb, int g, int row0, int tid) {
    const int t   = g / CHUNKS;
    const int c   = g % CHUNKS;
    const int seg = c >> 3;
    const int kl  = (c & 7) * BK;
    const int e0  = t * BN;
    const int buf = g & 1;
    const __nv_bfloat16* za = (seg < 2)  ? g_z1 : g_z2;
    const __nv_bfloat16* eb = (seg == 1) ? g_e2 : g_e1;
    const uint32_t ab = sb + buf * STAGE;
    const uint32_t bb = ab + ABYTES;
#pragma unroll
    for (int it = 0; it < 8; it++) {           // A: 2048 x 16B
        int u = tid + it * 256;
        int m = u >> 3, q = u & 7;
        uint32_t dst = ab + m * 128 + ((q ^ (m & 7)) << 4);
        CP16(dst, za + (size_t)(row0 + m) * D + kl + q * 8);
    }
#pragma unroll
    for (int it = 0; it < 4; it++) {           // B: 1024 x 16B
        int u = tid + it * 256;
        int n = u >> 3, q = u & 7;
        uint32_t dst = bb + n * 128 + ((q ^ (n & 7)) << 4);
        CP16(dst, eb + (size_t)(e0 + n) * D + kl + q * 8);
    }
    CP_COMMIT();
}

__global__ void __launch_bounds__(256, 1) mma_argmax_kernel() {
    const uint32_t sb = smem_u32(smem_raw);
    const int tid  = threadIdx.x;
    const int wid  = tid >> 5;                 // 0..7
    const int lane = tid & 31;
    const int row0 = blockIdx.x * BM;
    const int wrow = wid * 32;                 // warp's first row within strip

    // ldmatrix lane addressing (precomputed pieces)
    const int a_lrow = (lane & 15);
    const int a_kx   = (lane >> 4);            // 0/1 -> +8 in k
    const int b_rowb = ((lane >> 4) << 3) + (lane & 7);
    const int b_kx   = (lane >> 3) & 1;

    float acc[2][16][4];
#pragma unroll
    for (int af = 0; af < 2; af++)
#pragma unroll
        for (int f = 0; f < 16; f++)
#pragma unroll
            for (int j = 0; j < 4; j++) acc[af][f][j] = 0.0f;

    Top2 tp[2][2];
#pragma unroll
    for (int af = 0; af < 2; af++)
#pragma unroll
        for (int rh = 0; rh < 2; rh++) tp[af][rh] = {-INFINITY, -INFINITY, 0, 0};

    load_chunk(sb, 0, row0, tid);

    for (int g = 0; g < TOTALG; g++) {
        if (g + 1 < TOTALG) {
            load_chunk(sb, g + 1, row0, tid);
            CP_WAIT(1);
        } else {
            CP_WAIT(0);
        }
        __syncthreads();

        const uint32_t ab = sb + (g & 1) * STAGE;
        const uint32_t bb = ab + ABYTES;
#pragma unroll
        for (int s = 0; s < 4; s++) {
            uint32_t a[2][4];
#pragma unroll
            for (int af = 0; af < 2; af++) {
                int row = wrow + af * 16 + a_lrow;
                int ku  = s * 2 + a_kx;
                uint32_t addr = ab + row * 128 + ((ku ^ (row & 7)) << 4);
                ldsm_x4(a[af][0], a[af][1], a[af][2], a[af][3], addr);
            }
#pragma unroll
            for (int gn = 0; gn < 8; gn++) {
                uint32_t b0, b1, b2, b3;
                int n  = gn * 16 + b_rowb;
                int ku = s * 2 + b_kx;
                uint32_t addr = bb + n * 128 + ((ku ^ (n & 7)) << 4);
                ldsm_x4(b0, b1, b2, b3, addr);
                mma_bf16(acc[0][gn * 2],     a[0][0], a[0][1], a[0][2], a[0][3], b0, b1);
                mma_bf16(acc[0][gn * 2 + 1], a[0][0], a[0][1], a[0][2], a[0][3], b2, b3);
                mma_bf16(acc[1][gn * 2],     a[1][0], a[1][1], a[1][2], a[1][3], b0, b1);
                mma_bf16(acc[1][gn * 2 + 1], a[1][0], a[1][1], a[1][2], a[1][3], b2, b3);
            }
        }

        if ((g % CHUNKS) == CHUNKS - 1) {
            // tile epilogue: scale by 1/||emb||, update top-2, reset acc
            const int e0 = (g / CHUNKS) * BN;
            const int c2 = (lane & 3) * 2;
#pragma unroll
            for (int af = 0; af < 2; af++)
#pragma unroll
                for (int f = 0; f < 16; f++) {
                    int col0 = e0 + f * 8 + c2;
                    float i0  = __ldg(&g_inv[col0]);
                    float i1v = __ldg(&g_inv[col0 + 1]);
                    t2_update(tp[af][0], acc[af][f][0] * i0,  col0);
                    t2_update(tp[af][0], acc[af][f][1] * i1v, col0 + 1);
                    t2_update(tp[af][1], acc[af][f][2] * i0,  col0);
                    t2_update(tp[af][1], acc[af][f][3] * i1v, col0 + 1);
#pragma unroll
                    for (int j = 0; j < 4; j++) acc[af][f][j] = 0.0f;
                }
        }
        __syncthreads();
    }

    // reduce top-2 across the 4 lanes sharing each row (lane%4 = 0..3)
#pragma unroll
    for (int af = 0; af < 2; af++)
#pragma unroll
        for (int rh = 0; rh < 2; rh++) {
#pragma unroll
            for (int o = 1; o < 4; o <<= 1) {
                float w1 = __shfl_xor_sync(0xffffffffu, tp[af][rh].v1, o);
                int   j1 = __shfl_xor_sync(0xffffffffu, tp[af][rh].i1, o);
                float w2 = __shfl_xor_sync(0xffffffffu, tp[af][rh].v2, o);
                int   j2 = __shfl_xor_sync(0xffffffffu, tp[af][rh].i2, o);
                t2_merge(tp[af][rh], w1, j1, w2, j2);
            }
        }
    if ((lane & 3) == 0) {
#pragma unroll
        for (int af = 0; af < 2; af++)
#pragma unroll
            for (int rh = 0; rh < 2; rh++) {
                int r = row0 + wrow + af * 16 + rh * 8 + (lane >> 2);
                g_i1[r] = tp[af][rh].i1;
                g_i2[r] = tp[af][rh].i2;
            }
    }
}

// ---------------- exact fp32 re-score of top-2 candidates ----------------
__global__ void fixup_kernel(const float* __restrict__ z, const float* __restrict__ emb) {
    int w    = (blockIdx.x * blockDim.x + threadIdx.x) >> 5;
    int lane = threadIdx.x & 31;
    int iA = g_i1[w], iB = g_i2[w];
    const float4* zr = (const float4*)(z + (size_t)w * D);
    const float4* ea = (const float4*)(emb + (size_t)iA * D);
    const float4* eb = (const float4*)(emb + (size_t)iB * D);
    float dA = 0.0f, dB = 0.0f;
    for (int k = lane; k < D / 4; k += 32) {
        float4 zv = zr[k], a = ea[k], b = eb[k];
        dA += zv.x * a.x + zv.y * a.y + zv.z * a.z + zv.w * a.w;
        dB += zv.x * b.x + zv.y * b.y + zv.z * b.z + zv.w * b.w;
    }
    for (int o = 16; o; o >>= 1) {
        dA += __shfl_down_sync(0xffffffffu, dA, o);
        dB += __shfl_down_sync(0xffffffffu, dB, o);
    }
    if (lane == 0) {
        float sA = dA * g_inv[iA];
        float sB = dB * g_inv[iB];
        int win = (sB > sA || (sB == sA && iB < iA)) ? iB : iA;
        g_idx[w] = win;
    }
}

// ---------------- gather + z_q_st + loss + counts + idx out ----------------
__global__ void gather_kernel(const float* __restrict__ z,
                              const float* __restrict__ emb,
                              float* __restrict__ out_zq,
                              float* __restrict__ out_idx) {
    __shared__ float sred[4];
    __shared__ float sbc;
    int n = blockIdx.x;
    int t = threadIdx.x;
    int e = g_idx[n];
    float inv_e = g_inv[e];

    float4 zv = ((const float4*)(z + (size_t)n * D))[t];
    float ss = zv.x * zv.x + zv.y * zv.y + zv.z * zv.z + zv.w * zv.w;
    for (int o = 16; o; o >>= 1) ss += __shfl_down_sync(0xffffffffu, ss, o);
    if ((t & 31) == 0) sred[t >> 5] = ss;
    __syncthreads();
    if (t == 0) sbc = sred[0] + sred[1] + sred[2] + sred[3];
    __syncthreads();
    float zinv = 1.0f / fmaxf(sqrtf(sbc), 1e-12f);

    float4 q = ((const float4*)(emb + (size_t)e * D))[t];
    q.x *= inv_e; q.y *= inv_e; q.z *= inv_e; q.w *= inv_e;

    float* o = out_zq + (size_t)n * D + t * 4;
    o[0] = q.x; o[1] = q.y; o[2] = q.z; o[3] = q.w;

    float dx = q.x - zv.x * zinv;
    float dy = q.y - zv.y * zinv;
    float dz = q.z - zv.z * zinv;
    float dw = q.w - zv.w * zinv;
    float ls = dx * dx + dy * dy + dz * dz + dw * dw;
    for (int o2 = 16; o2; o2 >>= 1) ls += __shfl_down_sync(0xffffffffu, ls, o2);
    if ((t & 31) == 0) sred[t >> 5] = ls;
    __syncthreads();
    if (t == 0) {
        atomicAdd(&g_loss, sred[0] + sred[1] + sred[2] + sred[3]);
        atomicAdd(&g_counts[e], 1.0f);
        out_idx[n] = (float)e;
    }
}

__global__ void finalize_kernel(float* __restrict__ out, int N) {
    __shared__ float sh[256];
    float h = 0.0f;
    float invN = 1.0f / (float)N;
    for (int i = threadIdx.x; i < NE; i += 256) {
        float p = g_counts[i] * invN;
        h -= p * logf(p + 1e-10f);
    }
    sh[threadIdx.x] = h;
    __syncthreads();
    for (int s = 128; s; s >>= 1) {
        if (threadIdx.x < s) sh[threadIdx.x] += sh[threadIdx.x + s];
        __syncthreads();
    }
    if (threadIdx.x == 0) {
        out[0] = g_loss * (1.0f + BETA) / ((float)N * (float)D);
        out[1 + (size_t)N * D + (size_t)N] = expf(sh[0]);
    }
}

// ---------------- launch ----------------
extern "C" void kernel_launch(void* const* d_in, const int* in_sizes, int n_in,
                              void* d_out, int out_size) {
    const float* z   = (const float*)d_in[0];
    const float* emb = (const float*)d_in[1];
    float* out = (float*)d_out;

    int ND = in_sizes[0];
    int N  = ND / D;            // 32768

    cudaFuncSetAttribute(mma_argmax_kernel,
                         cudaFuncAttributeMaxDynamicSharedMemorySize, SMEM_SZ);

    zero_kernel<<<(NE + 255) / 256, 256>>>();
    embnorm_kernel<<<NE, 128>>>(emb);
    split_z_kernel<<<(N * D / 4 + 255) / 256, 256>>>(z);
    split_e_kernel<<<(NE * D / 4 + 255) / 256, 256>>>(emb);
    mma_argmax_kernel<<<N / BM, 256, SMEM_SZ>>>();
    fixup_kernel<<<N / 8, 256>>>(z, emb);
    // output layout (tuple order, all as float32):
    // [0] loss | [1 .. 1+N*D) z_q_st | [1+N*D .. 1+N*D+N) idx | [last] perplexity
    gather_kernel<<<N, 128>>>(z, emb, out + 1, out + 1 + (size_t)ND);
    finalize_kernel<<<1, 256>>>(out, N);
}

// round 9
// speedup vs baseline: 4.3676x; 1.5701x over previous
#include <cuda_runtime.h>
#include <cuda_bf16.h>
#include <cstdint>
#include <math.h>

#define D     512
#define NE    8192
#define NMAX  32768
#define BETA  0.25f

#define BM      256
#define BN      128
#define BK      64
#define NTILES  (NE / BN)          // 64
#define CHUNKS  8                  // per tile: 8 chunks of 64 (K = 512, plain bf16)
#define TOTALG  (NTILES * CHUNKS)  // 512

// ---------------- device scratch ----------------
__device__ __nv_bfloat16 g_zb[(size_t)NMAX * D];
__device__ __nv_bfloat16 g_eb[(size_t)NE * D];
__device__ float g_inv[NE];
__device__ float g_counts[NE];
__device__ int   g_idx[NMAX];
__device__ int   g_cand[(size_t)NMAX * 4];
__device__ float g_loss;

// ---------------- PTX helpers ----------------
__device__ __forceinline__ uint32_t smem_u32(const void* p) {
    uint32_t a;
    asm("{ .reg .u64 t; cvta.to.shared.u64 t, %1; cvt.u32.u64 %0, t; }" : "=r"(a) : "l"(p));
    return a;
}
#define CP16(dst, src) \
    asm volatile("cp.async.cg.shared.global [%0], [%1], 16;" :: "r"(dst), "l"(src) : "memory")
#define CP_COMMIT() asm volatile("cp.async.commit_group;" ::: "memory")
#define CP_WAIT(n)  asm volatile("cp.async.wait_group %0;" :: "n"(n) : "memory")

__device__ __forceinline__ void ldsm_x4(uint32_t& r0, uint32_t& r1, uint32_t& r2, uint32_t& r3,
                                        uint32_t addr) {
    asm volatile("ldmatrix.sync.aligned.m8n8.x4.shared.b16 {%0,%1,%2,%3}, [%4];"
                 : "=r"(r0), "=r"(r1), "=r"(r2), "=r"(r3) : "r"(addr));
}
__device__ __forceinline__ void mma_bf16(float* d, uint32_t a0, uint32_t a1, uint32_t a2,
                                         uint32_t a3, uint32_t b0, uint32_t b1) {
    asm volatile("mma.sync.aligned.m16n8k16.row.col.f32.bf16.bf16.f32 "
                 "{%0,%1,%2,%3}, {%4,%5,%6,%7}, {%8,%9}, {%0,%1,%2,%3};"
                 : "+f"(d[0]), "+f"(d[1]), "+f"(d[2]), "+f"(d[3])
                 : "r"(a0), "r"(a1), "r"(a2), "r"(a3), "r"(b0), "r"(b1));
}

// ---------------- small kernels ----------------
__global__ void zero_kernel() {
    int i = blockIdx.x * blockDim.x + threadIdx.x;
    if (i < NE) g_counts[i] = 0.0f;
    if (i == 0) g_loss = 0.0f;
}

__global__ void embnorm_kernel(const float* __restrict__ emb) {
    int e = blockIdx.x;
    const float4* row = (const float4*)(emb + (size_t)e * D);
    float ss = 0.0f;
    for (int i = threadIdx.x; i < D / 4; i += 128) {
        float4 v = row[i];
        ss += v.x * v.x + v.y * v.y + v.z * v.z + v.w * v.w;
    }
    for (int o = 16; o; o >>= 1) ss += __shfl_down_sync(0xffffffffu, ss, o);
    __shared__ float s[4];
    if ((threadIdx.x & 31) == 0) s[threadIdx.x >> 5] = ss;
    __syncthreads();
    if (threadIdx.x == 0) {
        ss = s[0] + s[1] + s[2] + s[3];
        g_inv[e] = 1.0f / fmaxf(sqrtf(ss), 1e-12f);
    }
}

// NOTE: device arrays are referenced inside device code (NOT passed from host —
// taking a __device__ symbol's address in host code is UB and was the R5/R7 bug).
__global__ void cvt_z_kernel(const float* __restrict__ z) {
    size_t i = (size_t)blockIdx.x * blockDim.x + threadIdx.x;
    float4 v = ((const float4*)z)[i];
    __nv_bfloat162* dst = (__nv_bfloat162*)g_zb;
    dst[i * 2]     = __nv_bfloat162(__float2bfloat16_rn(v.x), __float2bfloat16_rn(v.y));
    dst[i * 2 + 1] = __nv_bfloat162(__float2bfloat16_rn(v.z), __float2bfloat16_rn(v.w));
}
__global__ void cvt_e_kernel(const float* __restrict__ emb) {
    size_t i = (size_t)blockIdx.x * blockDim.x + threadIdx.x;
    float4 v = ((const float4*)emb)[i];
    __nv_bfloat162* dst = (__nv_bfloat162*)g_eb;
    dst[i * 2]     = __nv_bfloat162(__float2bfloat16_rn(v.x), __float2bfloat16_rn(v.y));
    dst[i * 2 + 1] = __nv_bfloat162(__float2bfloat16_rn(v.z), __float2bfloat16_rn(v.w));
}

// ---------------- HMMA GEMM (bf16, K=512) + fused top-4 argmax ----------------
// 128 CTAs x 256 threads (8 warps). CTA = 256-row strip, loops 64 N-tiles.
// Warp w: rows w*32..w*32+31 (two 16-row A fragments) x all 128 tile cols.
// Per-thread sorted top-4, merged across the 4 lanes per row; 4 candidates per
// row are then exactly re-scored in fp32 (fixup_kernel) -> idx is exact.
#define ABYTES  (BM * BK * 2)      // 32768
#define BBYTES  (BN * BK * 2)      // 16384
#define STAGE   (ABYTES + BBYTES)  // 49152
#define SMEM_SZ (2 * STAGE)        // 98304

extern __shared__ char smem_raw[];

struct Top4 { float v[4]; int i[4]; };

__device__ __forceinline__ void t4_update(Top4& t, float s, int c) {
    if (s <= t.v[3]) return;
    if (s > t.v[1]) {
        if (s > t.v[0]) {
            t.v[3] = t.v[2]; t.i[3] = t.i[2];
            t.v[2] = t.v[1]; t.i[2] = t.i[1];
            t.v[1] = t.v[0]; t.i[1] = t.i[0];
            t.v[0] = s;      t.i[0] = c;
        } else {
            t.v[3] = t.v[2]; t.i[3] = t.i[2];
            t.v[2] = t.v[1]; t.i[2] = t.i[1];
            t.v[1] = s;      t.i[1] = c;
        }
    } else {
        if (s > t.v[2]) {
            t.v[3] = t.v[2]; t.i[3] = t.i[2];
            t.v[2] = s;      t.i[2] = c;
        } else {
            t.v[3] = s;      t.i[3] = c;
        }
    }
}

__device__ __forceinline__ void load_chunk(uint32_t sb, int g, int row0, int tid) {
    const int t   = g >> 3;
    const int kl  = (g & 7) * BK;
    const int e0  = t * BN;
    const int buf = g & 1;
    const uint32_t ab = sb + buf * STAGE;
    const uint32_t bb = ab + ABYTES;
#pragma unroll
    for (int it = 0; it < 8; it++) {           // A: 2048 x 16B
        int u = tid + it * 256;
        int m = u >> 3, q = u & 7;
        uint32_t dst = ab + m * 128 + ((q ^ (m & 7)) << 4);
        CP16(dst, g_zb + (size_t)(row0 + m) * D + kl + q * 8);
    }
#pragma unroll
    for (int it = 0; it < 4; it++) {           // B: 1024 x 16B
        int u = tid + it * 256;
        int n = u >> 3, q = u & 7;
        uint32_t dst = bb + n * 128 + ((q ^ (n & 7)) << 4);
        CP16(dst, g_eb + (size_t)(e0 + n) * D + kl + q * 8);
    }
    CP_COMMIT();
}

__global__ void __launch_bounds__(256, 1) mma_argmax_kernel() {
    const uint32_t sb = smem_u32(smem_raw);
    const int tid  = threadIdx.x;
    const int wid  = tid >> 5;                 // 0..7
    const int lane = tid & 31;
    const int row0 = blockIdx.x * BM;
    const int wrow = wid * 32;                 // warp's first row within strip

    // ldmatrix lane addressing (precomputed pieces)
    const int a_lrow = (lane & 15);
    const int a_kx   = (lane >> 4);            // 0/1 -> +8 in k
    const int b_rowb = ((lane >> 4) << 3) + (lane & 7);
    const int b_kx   = (lane >> 3) & 1;

    float acc[2][16][4];
#pragma unroll
    for (int af = 0; af < 2; af++)
#pragma unroll
        for (int f = 0; f < 16; f++)
#pragma unroll
            for (int j = 0; j < 4; j++) acc[af][f][j] = 0.0f;

    Top4 tp[2][2];
#pragma unroll
    for (int af = 0; af < 2; af++)
#pragma unroll
        for (int rh = 0; rh < 2; rh++)
#pragma unroll
            for (int k = 0; k < 4; k++) { tp[af][rh].v[k] = -INFINITY; tp[af][rh].i[k] = 0; }

    load_chunk(sb, 0, row0, tid);

    for (int g = 0; g < TOTALG; g++) {
        if (g + 1 < TOTALG) {
            load_chunk(sb, g + 1, row0, tid);
            CP_WAIT(1);
        } else {
            CP_WAIT(0);
        }
        __syncthreads();

        const uint32_t ab = sb + (g & 1) * STAGE;
        const uint32_t bb = ab + ABYTES;
#pragma unroll
        for (int s = 0; s < 4; s++) {
            uint32_t a[2][4];
#pragma unroll
            for (int af = 0; af < 2; af++) {
                int row = wrow + af * 16 + a_lrow;
                int ku  = s * 2 + a_kx;
                uint32_t addr = ab + row * 128 + ((ku ^ (row & 7)) << 4);
                ldsm_x4(a[af][0], a[af][1], a[af][2], a[af][3], addr);
            }
#pragma unroll
            for (int gn = 0; gn < 8; gn++) {
                uint32_t b0, b1, b2, b3;
                int n  = gn * 16 + b_rowb;
                int ku = s * 2 + b_kx;
                uint32_t addr = bb + n * 128 + ((ku ^ (n & 7)) << 4);
                ldsm_x4(b0, b1, b2, b3, addr);
                mma_bf16(acc[0][gn * 2],     a[0][0], a[0][1], a[0][2], a[0][3], b0, b1);
                mma_bf16(acc[0][gn * 2 + 1], a[0][0], a[0][1], a[0][2], a[0][3], b2, b3);
                mma_bf16(acc[1][gn * 2],     a[1][0], a[1][1], a[1][2], a[1][3], b0, b1);
                mma_bf16(acc[1][gn * 2 + 1], a[1][0], a[1][1], a[1][2], a[1][3], b2, b3);
            }
        }

        if ((g & 7) == 7) {
            // tile epilogue: scale by 1/||emb||, update top-4, reset acc
            const int e0 = (g >> 3) * BN;
            const int c2 = (lane & 3) * 2;
#pragma unroll
            for (int af = 0; af < 2; af++)
#pragma unroll
                for (int f = 0; f < 16; f++) {
                    int col0 = e0 + f * 8 + c2;
                    float i0  = __ldg(&g_inv[col0]);
                    float i1v = __ldg(&g_inv[col0 + 1]);
                    t4_update(tp[af][0], acc[af][f][0] * i0,  col0);
                    t4_update(tp[af][0], acc[af][f][1] * i1v, col0 + 1);
                    t4_update(tp[af][1], acc[af][f][2] * i0,  col0);
                    t4_update(tp[af][1], acc[af][f][3] * i1v, col0 + 1);
#pragma unroll
                    for (int j = 0; j < 4; j++) acc[af][f][j] = 0.0f;
                }
        }
        __syncthreads();
    }

    // merge top-4 across the 4 lanes sharing each row (lane%4 = 0..3)
#pragma unroll
    for (int af = 0; af < 2; af++)
#pragma unroll
        for (int rh = 0; rh < 2; rh++) {
#pragma unroll
            for (int o = 1; o < 4; o <<= 1) {
                float ov[4]; int oi[4];
#pragma unroll
                for (int k = 0; k < 4; k++) {
                    ov[k] = __shfl_xor_sync(0xffffffffu, tp[af][rh].v[k], o);
                    oi[k] = __shfl_xor_sync(0xffffffffu, tp[af][rh].i[k], o);
                }
#pragma unroll
                for (int k = 0; k < 4; k++) t4_update(tp[af][rh], ov[k], oi[k]);
            }
        }
    if ((lane & 3) == 0) {
#pragma unroll
        for (int af = 0; af < 2; af++)
#pragma unroll
            for (int rh = 0; rh < 2; rh++) {
                int r = row0 + wrow + af * 16 + rh * 8 + (lane >> 2);
#pragma unroll
                for (int k = 0; k < 4; k++) g_cand[r * 4 + k] = tp[af][rh].i[k];
            }
    }
}

// ---------------- exact fp32 re-score of top-4 candidates ----------------
__global__ void fixup_kernel(const float* __restrict__ z, const float* __restrict__ emb) {
    int row  = (blockIdx.x * blockDim.x + threadIdx.x) >> 5;
    int lane = threadIdx.x & 31;
    const float4* zr = (const float4*)(z + (size_t)row * D);
    float4 zf[4];
#pragma unroll
    for (int j = 0; j < 4; j++) zf[j] = zr[lane + j * 32];

    float bv = -INFINITY;
    int   bi = 0x7fffffff;
#pragma unroll
    for (int c = 0; c < 4; c++) {
        int e = g_cand[row * 4 + c];
        const float4* er = (const float4*)(emb + (size_t)e * D);
        float d = 0.0f;
#pragma unroll
        for (int j = 0; j < 4; j++) {
            float4 ev = er[lane + j * 32];
            d += zf[j].x * ev.x + zf[j].y * ev.y + zf[j].z * ev.z + zf[j].w * ev.w;
        }
        for (int o = 16; o; o >>= 1) d += __shfl_down_sync(0xffffffffu, d, o);
        if (lane == 0) {
            float s = d * g_inv[e];
            if (s > bv || (s == bv && e < bi)) { bv = s; bi = e; }
        }
    }
    if (lane == 0) g_idx[row] = bi;
}

// ---------------- gather + z_q_st + loss + counts + idx out ----------------
__global__ void gather_kernel(const float* __restrict__ z,
                              const float* __restrict__ emb,
                              float* __restrict__ out_zq,
                              float* __restrict__ out_idx) {
    __shared__ float sred[4];
    __shared__ float sbc;
    int n = blockIdx.x;
    int t = threadIdx.x;
    int e = g_idx[n];
    float inv_e = g_inv[e];

    float4 zv = ((const float4*)(z + (size_t)n * D))[t];
    float ss = zv.x * zv.x + zv.y * zv.y + zv.z * zv.z + zv.w * zv.w;
    for (int o = 16; o; o >>= 1) ss += __shfl_down_sync(0xffffffffu, ss, o);
    if ((t & 31) == 0) sred[t >> 5] = ss;
    __syncthreads();
    if (t == 0) sbc = sred[0] + sred[1] + sred[2] + sred[3];
    __syncthreads();
    float zinv = 1.0f / fmaxf(sqrtf(sbc), 1e-12f);

    float4 q = ((const float4*)(emb + (size_t)e * D))[t];
    q.x *= inv_e; q.y *= inv_e; q.z *= inv_e; q.w *= inv_e;

    float* o = out_zq + (size_t)n * D + t * 4;
    o[0] = q.x; o[1] = q.y; o[2] = q.z; o[3] = q.w;

    float dx = q.x - zv.x * zinv;
    float dy = q.y - zv.y * zinv;
    float dz = q.z - zv.z * zinv;
    float dw = q.w - zv.w * zinv;
    float ls = dx * dx + dy * dy + dz * dz + dw * dw;
    for (int o2 = 16; o2; o2 >>= 1) ls += __shfl_down_sync(0xffffffffu, ls, o2);
    if ((t & 31) == 0) sred[t >> 5] = ls;
    __syncthreads();
    if (t == 0) {
        atomicAdd(&g_loss, sred[0] + sred[1] + sred[2] + sred[3]);
        atomicAdd(&g_counts[e], 1.0f);
        out_idx[n] = (float)e;
    }
}

__global__ void finalize_kernel(float* __restrict__ out, int N) {
    __shared__ float sh[256];
    float h = 0.0f;
    float invN = 1.0f / (float)N;
    for (int i = threadIdx.x; i < NE; i += 256) {
        float p = g_counts[i] * invN;
        h -= p * logf(p + 1e-10f);
    }
    sh[threadIdx.x] = h;
    __syncthreads();
    for (int s = 128; s; s >>= 1) {
        if (threadIdx.x < s) sh[threadIdx.x] += sh[threadIdx.x + s];
        __syncthreads();
    }
    if (threadIdx.x == 0) {
        out[0] = g_loss * (1.0f + BETA) / ((float)N * (float)D);
        out[1 + (size_t)N * D + (size_t)N] = expf(sh[0]);
    }
}

// ---------------- launch ----------------
extern "C" void kernel_launch(void* const* d_in, const int* in_sizes, int n_in,
                              void* d_out, int out_size) {
    const float* z   = (const float*)d_in[0];
    const float* emb = (const float*)d_in[1];
    float* out = (float*)d_out;

    int ND = in_sizes[0];
    int N  = ND / D;            // 32768

    cudaFuncSetAttribute(mma_argmax_kernel,
                         cudaFuncAttributeMaxDynamicSharedMemorySize, SMEM_SZ);

    zero_kernel<<<(NE + 255) / 256, 256>>>();
    embnorm_kernel<<<NE, 128>>>(emb);
    cvt_z_kernel<<<(N * D / 4) / 256, 256>>>(z);
    cvt_e_kernel<<<(NE * D / 4) / 256, 256>>>(emb);
    mma_argmax_kernel<<<N / BM, 256, SMEM_SZ>>>();
    fixup_kernel<<<N / 8, 256>>>(z, emb);
    // output layout (tuple order, all as float32):
    // [0] loss | [1 .. 1+N*D) z_q_st | [1+N*D .. 1+N*D+N) idx | [last] perplexity
    gather_kernel<<<N, 128>>>(z, emb, out + 1, out + 1 + (size_t)ND);
    finalize_kernel<<<1, 256>>>(out, N);
}

// round 10
// speedup vs baseline: 6.7734x; 1.5508x over previous
#include <cuda_runtime.h>
#include <cuda_bf16.h>
#include <cstdint>
#include <math.h>

#define D     512
#define NE    8192
#define NMAX  32768
#define BETA  0.25f

#define BM      256
#define BN      128
#define BK      64
#define NTILES  (NE / BN)          // 64
#define TOTALG  (NTILES * 8)       // 512 chunks of K=64

// ---------------- device scratch ----------------
__device__ __nv_bfloat16 g_zb[(size_t)NMAX * D];
__device__ __nv_bfloat16 g_eb[(size_t)NE * D];   // PRE-NORMALIZED emb (bf16)
__device__ float g_inv[NE];
__device__ float g_counts[NE];
__device__ int   g_idx[NMAX];
__device__ int   g_cand[(size_t)NMAX * 4];
__device__ float g_loss;

// ---------------- PTX helpers ----------------
__device__ __forceinline__ uint32_t smem_u32(const void* p) {
    uint32_t a;
    asm("{ .reg .u64 t; cvta.to.shared.u64 t, %1; cvt.u32.u64 %0, t; }" : "=r"(a) : "l"(p));
    return a;
}
#define CP16(dst, src) \
    asm volatile("cp.async.cg.shared.global [%0], [%1], 16;" :: "r"(dst), "l"(src) : "memory")
#define CP_COMMIT() asm volatile("cp.async.commit_group;" ::: "memory")
#define CP_WAIT(n)  asm volatile("cp.async.wait_group %0;" :: "n"(n) : "memory")

__device__ __forceinline__ void ldsm_x4(uint32_t& r0, uint32_t& r1, uint32_t& r2, uint32_t& r3,
                                        uint32_t addr) {
    asm volatile("ldmatrix.sync.aligned.m8n8.x4.shared.b16 {%0,%1,%2,%3}, [%4];"
                 : "=r"(r0), "=r"(r1), "=r"(r2), "=r"(r3) : "r"(addr));
}
__device__ __forceinline__ void mma_bf16(float* d, uint32_t a0, uint32_t a1, uint32_t a2,
                                         uint32_t a3, uint32_t b0, uint32_t b1) {
    asm volatile("mma.sync.aligned.m16n8k16.row.col.f32.bf16.bf16.f32 "
                 "{%0,%1,%2,%3}, {%4,%5,%6,%7}, {%8,%9}, {%0,%1,%2,%3};"
                 : "+f"(d[0]), "+f"(d[1]), "+f"(d[2]), "+f"(d[3])
                 : "r"(a0), "r"(a1), "r"(a2), "r"(a3), "r"(b0), "r"(b1));
}

// ---------------- small kernels ----------------
__global__ void zero_kernel() {
    int i = blockIdx.x * blockDim.x + threadIdx.x;
    if (i < NE) g_counts[i] = 0.0f;
    if (i == 0) g_loss = 0.0f;
}

// one block per emb row: compute inv norm, store it, write normalized bf16 row
__global__ void embprep_kernel(const float* __restrict__ emb) {
    int e = blockIdx.x;
    int t = threadIdx.x;   // 128 threads, 4 floats each
    const float4* row = (const float4*)(emb + (size_t)e * D);
    float4 v = row[t];
    float ss = v.x * v.x + v.y * v.y + v.z * v.z + v.w * v.w;
    for (int o = 16; o; o >>= 1) ss += __shfl_down_sync(0xffffffffu, ss, o);
    __shared__ float s[4];
    __shared__ float sinv;
    if ((t & 31) == 0) s[t >> 5] = ss;
    __syncthreads();
    if (t == 0) {
        float tot = s[0] + s[1] + s[2] + s[3];
        float inv = 1.0f / fmaxf(sqrtf(tot), 1e-12f);
        g_inv[e] = inv;
        sinv = inv;
    }
    __syncthreads();
    float inv = sinv;
    __nv_bfloat162* dst = (__nv_bfloat162*)g_eb + (size_t)e * (D / 2) + t * 2;
    dst[0] = __nv_bfloat162(__float2bfloat16_rn(v.x * inv), __float2bfloat16_rn(v.y * inv));
    dst[1] = __nv_bfloat162(__float2bfloat16_rn(v.z * inv), __float2bfloat16_rn(v.w * inv));
}

__global__ void cvt_z_kernel(const float* __restrict__ z) {
    size_t i = (size_t)blockIdx.x * blockDim.x + threadIdx.x;
    float4 v = ((const float4*)z)[i];
    __nv_bfloat162* dst = (__nv_bfloat162*)g_zb;
    dst[i * 2]     = __nv_bfloat162(__float2bfloat16_rn(v.x), __float2bfloat16_rn(v.y));
    dst[i * 2 + 1] = __nv_bfloat162(__float2bfloat16_rn(v.z), __float2bfloat16_rn(v.w));
}

// ---------------- HMMA GEMM (bf16, K=512) + fused top-4 argmax ----------------
// 128 CTAs x 256 threads (8 warps). CTA = 256-row strip, loops 64 N-tiles.
// B is pre-normalized -> acc IS the cosine score; epilogue has no global loads.
// 3-stage cp.async pipeline, ONE __syncthreads per chunk.
#define ABYTES  (BM * BK * 2)      // 32768
#define BBYTES  (BN * BK * 2)      // 16384
#define STAGE   (ABYTES + BBYTES)  // 49152
#define NSTG    3
#define SMEM_SZ (NSTG * STAGE)     // 147456

extern __shared__ char smem_raw[];

struct Top4 { float v[4]; int i[4]; };

__device__ __forceinline__ void t4_update(Top4& t, float s, int c) {
    if (s <= t.v[3]) return;
    if (s > t.v[1]) {
        if (s > t.v[0]) {
            t.v[3] = t.v[2]; t.i[3] = t.i[2];
            t.v[2] = t.v[1]; t.i[2] = t.i[1];
            t.v[1] = t.v[0]; t.i[1] = t.i[0];
            t.v[0] = s;      t.i[0] = c;
        } else {
            t.v[3] = t.v[2]; t.i[3] = t.i[2];
            t.v[2] = t.v[1]; t.i[2] = t.i[1];
            t.v[1] = s;      t.i[1] = c;
        }
    } else {
        if (s > t.v[2]) {
            t.v[3] = t.v[2]; t.i[3] = t.i[2];
            t.v[2] = s;      t.i[2] = c;
        } else {
            t.v[3] = s;      t.i[3] = c;
        }
    }
}

__device__ __forceinline__ void load_chunk(uint32_t sb, int g, int stage, int row0, int tid) {
    const int kl = (g & 7) * BK;
    const int e0 = (g >> 3) * BN;
    const uint32_t ab = sb + stage * STAGE;
    const uint32_t bb = ab + ABYTES;
#pragma unroll
    for (int it = 0; it < 8; it++) {           // A: 2048 x 16B
        int u = tid + it * 256;
        int m = u >> 3, q = u & 7;
        uint32_t dst = ab + m * 128 + ((q ^ (m & 7)) << 4);
        CP16(dst, g_zb + (size_t)(row0 + m) * D + kl + q * 8);
    }
#pragma unroll
    for (int it = 0; it < 4; it++) {           // B: 1024 x 16B
        int u = tid + it * 256;
        int n = u >> 3, q = u & 7;
        uint32_t dst = bb + n * 128 + ((q ^ (n & 7)) << 4);
        CP16(dst, g_eb + (size_t)(e0 + n) * D + kl + q * 8);
    }
    CP_COMMIT();
}

__global__ void __launch_bounds__(256, 1) mma_argmax_kernel() {
    const uint32_t sb = smem_u32(smem_raw);
    const int tid  = threadIdx.x;
    const int wid  = tid >> 5;                 // 0..7
    const int lane = tid & 31;
    const int row0 = blockIdx.x * BM;
    const int wrow = wid * 32;

    const int a_lrow = (lane & 15);
    const int a_kx   = (lane >> 4);
    const int b_rowb = ((lane >> 4) << 3) + (lane & 7);
    const int b_kx   = (lane >> 3) & 1;

    float acc[2][16][4];
#pragma unroll
    for (int af = 0; af < 2; af++)
#pragma unroll
        for (int f = 0; f < 16; f++)
#pragma unroll
            for (int j = 0; j < 4; j++) acc[af][f][j] = 0.0f;

    Top4 tp[2][2];
#pragma unroll
    for (int af = 0; af < 2; af++)
#pragma unroll
        for (int rh = 0; rh < 2; rh++)
#pragma unroll
            for (int k = 0; k < 4; k++) { tp[af][rh].v[k] = -INFINITY; tp[af][rh].i[k] = 0; }

    load_chunk(sb, 0, 0, row0, tid);
    load_chunk(sb, 1, 1, row0, tid);

    int st = 0;
    for (int g = 0; g < TOTALG; g++) {
        // wait for chunk g (allow next chunk's group to stay pending)
        if (g + 1 < TOTALG) CP_WAIT(1); else CP_WAIT(0);
        __syncthreads();   // all warps: done reading stage (g-1)%3, chunk g visible

        // prefetch g+2 into the stage just freed ((g-1)%3 == (g+2)%3)
        if (g + 2 < TOTALG) {
            int st2 = st + 2; if (st2 >= NSTG) st2 -= NSTG;
            load_chunk(sb, g + 2, st2, row0, tid);
        }

        const uint32_t ab = sb + st * STAGE;
        const uint32_t bb = ab + ABYTES;
#pragma unroll
        for (int s = 0; s < 4; s++) {
            uint32_t a[2][4];
#pragma unroll
            for (int af = 0; af < 2; af++) {
                int row = wrow + af * 16 + a_lrow;
                int ku  = s * 2 + a_kx;
                uint32_t addr = ab + row * 128 + ((ku ^ (row & 7)) << 4);
                ldsm_x4(a[af][0], a[af][1], a[af][2], a[af][3], addr);
            }
#pragma unroll
            for (int gn = 0; gn < 8; gn++) {
                uint32_t b0, b1, b2, b3;
                int n  = gn * 16 + b_rowb;
                int ku = s * 2 + b_kx;
                uint32_t addr = bb + n * 128 + ((ku ^ (n & 7)) << 4);
                ldsm_x4(b0, b1, b2, b3, addr);
                mma_bf16(acc[0][gn * 2],     a[0][0], a[0][1], a[0][2], a[0][3], b0, b1);
                mma_bf16(acc[0][gn * 2 + 1], a[0][0], a[0][1], a[0][2], a[0][3], b2, b3);
                mma_bf16(acc[1][gn * 2],     a[1][0], a[1][1], a[1][2], a[1][3], b0, b1);
                mma_bf16(acc[1][gn * 2 + 1], a[1][0], a[1][1], a[1][2], a[1][3], b2, b3);
            }
        }

        if ((g & 7) == 7) {
            // tile epilogue: acc IS the score (B pre-normalized); no loads
            const int e0 = (g >> 3) * BN;
            const int c2 = (lane & 3) * 2;
#pragma unroll
            for (int af = 0; af < 2; af++)
#pragma unroll
                for (int f = 0; f < 16; f++) {
                    int col0 = e0 + f * 8 + c2;
                    t4_update(tp[af][0], acc[af][f][0], col0);
                    t4_update(tp[af][0], acc[af][f][1], col0 + 1);
                    t4_update(tp[af][1], acc[af][f][2], col0);
                    t4_update(tp[af][1], acc[af][f][3], col0 + 1);
#pragma unroll
                    for (int j = 0; j < 4; j++) acc[af][f][j] = 0.0f;
                }
        }
        st = st + 1; if (st >= NSTG) st -= NSTG;
    }

    // merge top-4 across the 4 lanes sharing each row
#pragma unroll
    for (int af = 0; af < 2; af++)
#pragma unroll
        for (int rh = 0; rh < 2; rh++) {
#pragma unroll
            for (int o = 1; o < 4; o <<= 1) {
                float ov[4]; int oi[4];
#pragma unroll
                for (int k = 0; k < 4; k++) {
                    ov[k] = __shfl_xor_sync(0xffffffffu, tp[af][rh].v[k], o);
                    oi[k] = __shfl_xor_sync(0xffffffffu, tp[af][rh].i[k], o);
                }
#pragma unroll
                for (int k = 0; k < 4; k++) t4_update(tp[af][rh], ov[k], oi[k]);
            }
        }
    if ((lane & 3) == 0) {
#pragma unroll
        for (int af = 0; af < 2; af++)
#pragma unroll
            for (int rh = 0; rh < 2; rh++) {
                int r = row0 + wrow + af * 16 + rh * 8 + (lane >> 2);
#pragma unroll
                for (int k = 0; k < 4; k++) g_cand[r * 4 + k] = tp[af][rh].i[k];
            }
    }
}

// ---------------- exact fp32 re-score of top-4 candidates ----------------
__global__ void fixup_kernel(const float* __restrict__ z, const float* __restrict__ emb) {
    int row  = (blockIdx.x * blockDim.x + threadIdx.x) >> 5;
    int lane = threadIdx.x & 31;
    const float4* zr = (const float4*)(z + (size_t)row * D);
    float4 zf[4];
#pragma unroll
    for (int j = 0; j < 4; j++) zf[j] = zr[lane + j * 32];

    float bv = -INFINITY;
    int   bi = 0x7fffffff;
#pragma unroll
    for (int c = 0; c < 4; c++) {
        int e = g_cand[row * 4 + c];
        const float4* er = (const float4*)(emb + (size_t)e * D);
        float d = 0.0f;
#pragma unroll
        for (int j = 0; j < 4; j++) {
            float4 ev = er[lane + j * 32];
            d += zf[j].x * ev.x + zf[j].y * ev.y + zf[j].z * ev.z + zf[j].w * ev.w;
        }
        for (int o = 16; o; o >>= 1) d += __shfl_down_sync(0xffffffffu, d, o);
        if (lane == 0) {
            float s = d * g_inv[e];
            if (s > bv || (s == bv && e < bi)) { bv = s; bi = e; }
        }
    }
    if (lane == 0) g_idx[row] = bi;
}

// ---------------- gather + z_q_st + loss + counts + idx out ----------------
__global__ void gather_kernel(const float* __restrict__ z,
                              const float* __restrict__ emb,
                              float* __restrict__ out_zq,
                              float* __restrict__ out_idx) {
    __shared__ float sred[4];
    __shared__ float sbc;
    int n = blockIdx.x;
    int t = threadIdx.x;
    int e = g_idx[n];
    float inv_e = g_inv[e];

    float4 zv = ((const float4*)(z + (size_t)n * D))[t];
    float ss = zv.x * zv.x + zv.y * zv.y + zv.z * zv.z + zv.w * zv.w;
    for (int o = 16; o; o >>= 1) ss += __shfl_down_sync(0xffffffffu, ss, o);
    if ((t & 31) == 0) sred[t >> 5] = ss;
    __syncthreads();
    if (t == 0) sbc = sred[0] + sred[1] + sred[2] + sred[3];
    __syncthreads();
    float zinv = 1.0f / fmaxf(sqrtf(sbc), 1e-12f);

    float4 q = ((const float4*)(emb + (size_t)e * D))[t];
    q.x *= inv_e; q.y *= inv_e; q.z *= inv_e; q.w *= inv_e;

    float* o = out_zq + (size_t)n * D + t * 4;
    o[0] = q.x; o[1] = q.y; o[2] = q.z; o[3] = q.w;

    float dx = q.x - zv.x * zinv;
    float dy = q.y - zv.y * zinv;
    float dz = q.z - zv.z * zinv;
    float dw = q.w - zv.w * zinv;
    float ls = dx * dx + dy * dy + dz * dz + dw * dw;
    for (int o2 = 16; o2; o2 >>= 1) ls += __shfl_down_sync(0xffffffffu, ls, o2);
    if ((t & 31) == 0) sred[t >> 5] = ls;
    __syncthreads();
    if (t == 0) {
        atomicAdd(&g_loss, sred[0] + sred[1] + sred[2] + sred[3]);
        atomicAdd(&g_counts[e], 1.0f);
        out_idx[n] = (float)e;
    }
}

__global__ void finalize_kernel(float* __restrict__ out, int N) {
    __shared__ float sh[256];
    float h = 0.0f;
    float invN = 1.0f / (float)N;
    for (int i = threadIdx.x; i < NE; i += 256) {
        float p = g_counts[i] * invN;
        h -= p * logf(p + 1e-10f);
    }
    sh[threadIdx.x] = h;
    __syncthreads();
    for (int s = 128; s; s >>= 1) {
        if (threadIdx.x < s) sh[threadIdx.x] += sh[threadIdx.x + s];
        __syncthreads();
    }
    if (threadIdx.x == 0) {
        out[0] = g_loss * (1.0f + BETA) / ((float)N * (float)D);
        out[1 + (size_t)N * D + (size_t)N] = expf(sh[0]);
    }
}

// ---------------- launch ----------------
extern "C" void kernel_launch(void* const* d_in, const int* in_sizes, int n_in,
                              void* d_out, int out_size) {
    const float* z   = (const float*)d_in[0];
    const float* emb = (const float*)d_in[1];
    float* out = (float*)d_out;

    int ND = in_sizes[0];
    int N  = ND / D;            // 32768

    cudaFuncSetAttribute(mma_argmax_kernel,
                         cudaFuncAttributeMaxDynamicSharedMemorySize, SMEM_SZ);

    zero_kernel<<<(NE + 255) / 256, 256>>>();
    embprep_kernel<<<NE, 128>>>(emb);
    cvt_z_kernel<<<(N * D / 4) / 256, 256>>>(z);
    mma_argmax_kernel<<<N / BM, 256, SMEM_SZ>>>();
    fixup_kernel<<<N / 8, 256>>>(z, emb);
    // output layout (tuple order, all as float32):
    // [0] loss | [1 .. 1+N*D) z_q_st | [1+N*D .. 1+N*D+N) idx | [last] perplexity
    gather_kernel<<<N, 128>>>(z, emb, out + 1, out + 1 + (size_t)ND);
    finalize_kernel<<<1, 256>>>(out, N);
}